// round 8
// baseline (speedup 1.0000x reference)
#include <cuda_runtime.h>
#include <cstdint>

#define BATCH   8
#define CH      256
#define HH      80
#define WW      80
#define HW      (HH*WW)          // 6400
#define HW2     (HW/2)           // 3200 float2 per channel
#define OC      32
#define GROUPS  4
#define OH      160
#define OW      160
#define OHW     (OH*OW)          // 25600

#define SC      16               // channels per conv stage
#define NSTAGE  (CH/SC)          // 16

typedef unsigned long long ull;

// scratch for conv output: 8*32*6400 floats = 6.55 MB
__device__ float g_off[BATCH * OC * HW];

__device__ __forceinline__ ull pack2(float a, float b) {
    ull r;
    asm("mov.b64 %0, {%1, %2};" : "=l"(r) : "f"(a), "f"(b));
    return r;
}

__device__ __forceinline__ ull ffma2(ull a, ull b, ull c) {
    ull d;
    asm("fma.rn.f32x2 %0, %1, %2, %3;" : "=l"(d) : "l"(a), "l"(b), "l"(c));
    return d;
}

// ---------------------------------------------------------------------------
// Kernel 1 (v7): 1x1 conv. 800 blocks x 128 thr (4 warps).
// Lane = one float2 position; warp = 8 output channels; block = 32 float2
// positions x all 32 oc (x staged once through smem -> 4x crossbar
// redundancy instead of 8x). Double-buffered 16-channel stages.
// smem = 32KB weights + 8KB x = 40KB -> 5.4 blocks/SM, 21.6 warps/SM.
// ---------------------------------------------------------------------------
__global__ void __launch_bounds__(128)
conv_off_kernel(const float* __restrict__ x,
                const float* __restrict__ wq,
                const float* __restrict__ bias) {
    __shared__ float ws[CH * OC];        // [c][o], 32 KB
    __shared__ ull   xs[2][SC][32];      // 2 x 4 KB

    int tid = threadIdx.x;
    for (int idx = tid; idx < CH * OC; idx += 128) {
        int o = idx >> 8;                // coalesced over c
        int c = idx & 255;
        ws[c * OC + o] = __ldg(&wq[o * CH + c]);
    }

    int b  = blockIdx.x / 100;
    int pb = (blockIdx.x % 100) * 32;    // float2 base within channel
    const ull* xb = reinterpret_cast<const ull*>(x) + (size_t)b * CH * HW2;

    int cl0 = tid >> 5;                  // 0..3
    int q0  = tid & 31;

    // prologue: stage 0 (channels 0..15), 4 rows per thread
    ull r[4];
#pragma unroll
    for (int k = 0; k < 4; k++)
        r[k] = __ldg(xb + (size_t)(cl0 + 4 * k) * HW2 + pb + q0);
#pragma unroll
    for (int k = 0; k < 4; k++)
        xs[0][cl0 + 4 * k][q0] = r[k];
    __syncthreads();                     // covers ws fill + stage 0

    int lane = tid & 31;
    int og   = tid >> 5;                 // 8 oc per warp
    const float* wso = ws + og * 8;

    ull acc[8];
#pragma unroll
    for (int o = 0; o < 8; o++) acc[o] = 0ULL;

#pragma unroll 1
    for (int st = 0; st < NSTAGE; st++) {
        int cb  = st * SC;
        int buf = st & 1;

        if (st + 1 < NSTAGE) {
#pragma unroll
            for (int k = 0; k < 4; k++)
                r[k] = __ldg(xb + (size_t)(cb + SC + cl0 + 4 * k) * HW2 + pb + q0);
        }

#pragma unroll
        for (int cl = 0; cl < SC; cl++) {
            ull xv = xs[buf][cl][lane];
            const float* wr = wso + (cb + cl) * OC;
            float4 wA = *reinterpret_cast<const float4*>(wr);      // bcast LDS.128
            float4 wB = *reinterpret_cast<const float4*>(wr + 4);
            acc[0] = ffma2(xv, pack2(wA.x, wA.x), acc[0]);
            acc[1] = ffma2(xv, pack2(wA.y, wA.y), acc[1]);
            acc[2] = ffma2(xv, pack2(wA.z, wA.z), acc[2]);
            acc[3] = ffma2(xv, pack2(wA.w, wA.w), acc[3]);
            acc[4] = ffma2(xv, pack2(wB.x, wB.x), acc[4]);
            acc[5] = ffma2(xv, pack2(wB.y, wB.y), acc[5]);
            acc[6] = ffma2(xv, pack2(wB.z, wB.z), acc[6]);
            acc[7] = ffma2(xv, pack2(wB.w, wB.w), acc[7]);
        }

        __syncthreads();                 // everyone done reading this stage pair
        if (st + 1 < NSTAGE) {
#pragma unroll
            for (int k = 0; k < 4; k++)
                xs[buf ^ 1][cl0 + 4 * k][q0] = r[k];
            __syncthreads();             // next buffer ready
        }
    }

    float2* offp = reinterpret_cast<float2*>(g_off) + (size_t)b * OC * HW2;
#pragma unroll
    for (int o = 0; o < 8; o++) {
        int oc = og * 8 + o;
        float bo = __ldg(&bias[oc]);
        float2 v;
        v.x = __uint_as_float((unsigned)(acc[o] & 0xffffffffULL)) + bo;
        v.y = __uint_as_float((unsigned)(acc[o] >> 32)) + bo;
        offp[(size_t)oc * HW2 + pb + lane] = v;
    }
}

// ---------------------------------------------------------------------------
// Kernel 2 (v7): tiled bilinear sampling.
// Thread = (b, gi, 2x2 input pixels, 16-ch chunk) -> 4x4 outputs/channel from
// 16 static taps. Weights packed (wx,wy) float2 in smem (16 LDS.64/ch).
// Tap rows loaded as LDG.32 + LDG.64 + LDG.32 with clamped endpoints
// (branch-free, border-correct, 12 loads/ch instead of 16).
// ---------------------------------------------------------------------------
__device__ __noinline__ void sample_fallback(
    const float* __restrict__ offb, const float* __restrict__ bp,
    float* __restrict__ opb, int gi, int hbase, int wbase, int ohb, int owb)
{
    for (int c = 0; c < 16; c++) {
        const float* pc = bp + (size_t)c * HW;
        float* oc = opb + (size_t)c * OHW;
        for (int r = 0; r < 4; r++) {
            float vv[4];
            for (int s = 0; s < 4; s++) {
                int hprime = hbase + (r >> 1);
                int i = r & 1;
                int wprime = wbase + (s >> 1);
                int j = s & 1;
                int k = gi * 4 + i * 2 + j;
                const float* op2 = offb + hprime * WW + wprime;
                float offx = __ldg(op2 + (size_t)k * HW);
                float offy = __ldg(op2 + (size_t)(16 + k) * HW);
                float px = (float)wprime + 0.25f * (offx + (float)(2 * j - 1));
                float py = (float)hprime + 0.25f * (offy + (float)(2 * i - 1));
                float ix = fminf(fmaxf(px, 0.0f), (float)(WW - 1));
                float iy = fminf(fmaxf(py, 0.0f), (float)(HH - 1));
                float fx = floorf(ix), fy = floorf(iy);
                int x0 = (int)fx, y0 = (int)fy;
                float wx = ix - fx, wy = iy - fy;
                int x1 = min(x0 + 1, WW - 1);
                int y1 = min(y0 + 1, HH - 1);
                float a0 = __ldg(pc + y0 * WW + x0);
                float a1 = __ldg(pc + y0 * WW + x1);
                float a2 = __ldg(pc + y1 * WW + x0);
                float a3 = __ldg(pc + y1 * WW + x1);
                float h0 = fmaf(wx, a1 - a0, a0);
                float h1 = fmaf(wx, a3 - a2, a2);
                vv[s] = fmaf(wy, h1 - h0, h0);
            }
            float4 v4 = make_float4(vv[0], vv[1], vv[2], vv[3]);
            *reinterpret_cast<float4*>(oc + (size_t)(ohb + r) * OW + owb) = v4;
        }
    }
}

__global__ void __launch_bounds__(128, 6)
sample_kernel(const float* __restrict__ x, float* __restrict__ out) {
    __shared__ float2 sw[16][128];       // (wx,wy) per output per thread, 16 KB

    int tid = threadIdx.x;
    int t = blockIdx.x * 128 + tid;      // 204800 threads
    int wp = t % 40;  int u = t / 40;
    int hp = u % 40;  u /= 40;
    int cchunk = u & 3;  u >>= 2;
    int gi = u & 3;
    int b  = u >> 2;

    int hbase = 2 * hp, wbase = 2 * wp;

    const float* offb = g_off + (size_t)b * OC * HW;

    bool valid = true;
#pragma unroll
    for (int r = 0; r < 4; r++) {
        int hprime = hbase + (r >> 1);
        int i = r & 1;
#pragma unroll
        for (int s = 0; s < 4; s++) {
            int wprime = wbase + (s >> 1);
            int j = s & 1;
            int k = gi * 4 + i * 2 + j;
            const float* op2 = offb + hprime * WW + wprime;
            float offx = __ldg(op2 + (size_t)k * HW);
            float offy = __ldg(op2 + (size_t)(16 + k) * HW);
            float px = (float)wprime + 0.25f * (offx + (float)(2 * j - 1));
            float py = (float)hprime + 0.25f * (offy + (float)(2 * i - 1));
            float ix = fminf(fmaxf(px, 0.0f), (float)(WW - 1));
            float iy = fminf(fmaxf(py, 0.0f), (float)(HH - 1));
            int tx0 = (s >> 1) + (s & 1);
            int ty0 = (r >> 1) + (r & 1);
            float wx = ix - (float)(wbase - 1 + tx0);
            float wy = iy - (float)(hbase - 1 + ty0);
            sw[r * 4 + s][tid] = make_float2(wx, wy);   // own column: no sync
            valid = valid && (wx >= 0.0f) && (wx <= 1.0f)
                          && (wy >= 0.0f) && (wy <= 1.0f);
        }
    }

    int c0 = cchunk * 16;
    const float* bp = x + (size_t)(b * CH + gi * 64 + c0) * HW;
    int ohb = 4 * hp;
    int owb = 4 * wp;
    float* opb = out + (size_t)(b * CH + gi * 64 + c0) * OHW;

    if (!valid) {
        sample_fallback(offb, bp, opb, gi, hbase, wbase, ohb, owb);
        return;
    }

    // clamped tap rows and row-endpoint columns
    int rowo[4];
#pragma unroll
    for (int tq = 0; tq < 4; tq++)
        rowo[tq] = min(max(hbase - 1 + tq, 0), HH - 1) * WW;
    int colL = max(wbase - 1, 0);        // tap tx=0
    int colR = min(wbase + 2, WW - 1);   // tap tx=3

#pragma unroll 1
    for (int c = 0; c < 16; c++) {
        const float* pc = bp + (size_t)c * HW;
        float tv[16];
#pragma unroll
        for (int ty = 0; ty < 4; ty++) {
            const float* rowp = pc + rowo[ty];
            tv[ty * 4 + 0] = __ldg(rowp + colL);
            float2 mid = __ldg(reinterpret_cast<const float2*>(rowp + wbase));
            tv[ty * 4 + 1] = mid.x;
            tv[ty * 4 + 2] = mid.y;
            tv[ty * 4 + 3] = __ldg(rowp + colR);
        }

        float* oc = opb + (size_t)c * OHW;
#pragma unroll
        for (int r = 0; r < 4; r++) {
            float vv[4];
#pragma unroll
            for (int s = 0; s < 4; s++) {
                const int tx0 = (s >> 1) + (s & 1);
                const int ty0 = (r >> 1) + (r & 1);
                float a0 = tv[ty0 * 4 + tx0];
                float a1 = tv[ty0 * 4 + tx0 + 1];
                float a2 = tv[(ty0 + 1) * 4 + tx0];
                float a3 = tv[(ty0 + 1) * 4 + tx0 + 1];
                float2 wxy = sw[r * 4 + s][tid];
                float h0 = fmaf(wxy.x, a1 - a0, a0);
                float h1 = fmaf(wxy.x, a3 - a2, a2);
                vv[s] = fmaf(wxy.y, h1 - h0, h0);
            }
            float4 v4 = make_float4(vv[0], vv[1], vv[2], vv[3]);
            *reinterpret_cast<float4*>(oc + (size_t)(ohb + r) * OW + owb) = v4;
        }
    }
}

extern "C" void kernel_launch(void* const* d_in, const int* in_sizes, int n_in,
                              void* d_out, int out_size) {
    const float* x    = (const float*)d_in[0];   // [8,256,80,80]
    const float* wq   = (const float*)d_in[1];   // [32,256,1,1]
    const float* bias = (const float*)d_in[2];   // [32]
    float* out = (float*)d_out;                  // [8,256,160,160]

    conv_off_kernel<<<800, 128>>>(x, wq, bias);
    sample_kernel<<<1600, 128>>>(x, out);
}